// round 4
// baseline (speedup 1.0000x reference)
#include <cuda_runtime.h>

// Shape fixed by setup_inputs: B=32, N=65536, T=64, HIDDEN=16.
#define BB      32
#define NN      65536
#define TT      64
#define CHUNKS  64                 // chunks per row (1024 cells each)
#define CCELLS  1024               // cells per chunk: one u32 per lane
#define FULLM   0xFFFFFFFFu

typedef unsigned long long u64;
typedef unsigned int u32;

// 3-input mux over constant masks: next_bit = msk[L*4 + C*2 + R].
template <typename T>
__device__ __forceinline__ T mux3(T L, T C, T R,
                                  T m0, T m1, T m2, T m3,
                                  T m4, T m5, T m6, T m7) {
    T x0 = (R & m1) | (~R & m0);
    T x1 = (R & m3) | (~R & m2);
    T x2 = (R & m5) | (~R & m4);
    T x3 = (R & m7) | (~R & m6);
    T y0 = (C & x1) | (~C & x0);
    T y1 = (C & x3) | (~C & x2);
    return (L & y1) | (~L & y0);
}

__device__ __forceinline__ u32 pack_word32(const float* __restrict__ p) {
    u32 w = 0u;
    const float4* p4 = (const float4*)p;
#pragma unroll
    for (int k = 0; k < 8; k++) {
        float4 v = p4[k];
        u32 q = 0u;
        if (v.x > 0.5f) q |= 1u;
        if (v.y > 0.5f) q |= 2u;
        if (v.z > 0.5f) q |= 4u;
        if (v.w > 0.5f) q |= 8u;
        w |= q << (4 * k);
    }
    return w;
}

__device__ __forceinline__ u64 pack_word64(const float* __restrict__ p) {
    return (u64)pack_word32(p) | ((u64)pack_word32(p + 32) << 32);
}

// One warp per (row, chunk-of-1024-cells). Each lane owns one u32 (32 cells);
// neighbors via shuffle. Lanes 0/31 carry a 64-bit halo word each (63 steps
// < 64 halo bits, so beyond-halo garbage never reaches the chunk). Every step
// writes the chunk's fp32 slab with streaming float4 stores.
__global__ __launch_bounds__(64) void fused_kernel(
    const float* __restrict__ f0,
    const float* __restrict__ W1,   // (3,16)
    const float* __restrict__ b1,   // (16,)
    const float* __restrict__ W2,   // (16,1)
    const float* __restrict__ b2,   // (1,)
    float* __restrict__ out)
{
    __shared__ u32 smsk[8];
    const int tid = threadIdx.x;

    // Collapse the MLP controller to an 8-entry truth table.
    if (tid < 8) {
        const float l = (float)((tid >> 2) & 1);
        const float c = (float)((tid >> 1) & 1);
        const float r = (float)(tid & 1);
        float logit = b2[0];
#pragma unroll
        for (int h = 0; h < 16; h++) {
            float v = fmaf(l, W1[h], fmaf(c, W1[16 + h], fmaf(r, W1[32 + h], b1[h])));
            logit = fmaf(W2[h], fmaxf(v, 0.0f), logit);
        }
        smsk[tid] = (logit > 0.0f) ? ~0u : 0u;
    }
    __syncthreads();

    const u32 m0 = smsk[0], m1 = smsk[1], m2 = smsk[2], m3 = smsk[3];
    const u32 m4 = smsk[4], m5 = smsk[5], m6 = smsk[6], m7 = smsk[7];
    const u64 M0 = m0 ? ~0ULL : 0ULL, M1 = m1 ? ~0ULL : 0ULL;
    const u64 M2 = m2 ? ~0ULL : 0ULL, M3 = m3 ? ~0ULL : 0ULL;
    const u64 M4 = m4 ? ~0ULL : 0ULL, M5 = m5 ? ~0ULL : 0ULL;
    const u64 M6 = m6 ? ~0ULL : 0ULL, M7 = m7 ? ~0ULL : 0ULL;

    const int gw   = blockIdx.x * 2 + (tid >> 5);   // global warp 0..2047
    const int lane = tid & 31;
    const int row  = gw >> 6;                       // batch row
    const int ch   = gw & (CHUNKS - 1);             // chunk within row
    const bool first = (ch == 0), last = (ch == CHUNKS - 1);

    const size_t rowoff = (size_t)row * NN;
    const int cell0 = ch * CCELLS;

    // ---- t = 0 slab: copy f0 chunk verbatim (coalesced) ----
    const float4* src4 = (const float4*)(f0 + rowoff + cell0);
    float4* dst4 = (float4*)(out + rowoff + cell0);
#pragma unroll
    for (int k = 0; k < 8; k++)
        __stcs(dst4 + k * 32 + lane, __ldg(src4 + k * 32 + lane));

    // ---- pack this lane's 32 cells + 64-bit halos on lanes 0/31 ----
    u32 cur = pack_word32(f0 + rowoff + cell0 + lane * 32);
    u64 hl = 0ULL, hr = 0ULL;
    if (lane == 0 && !first)
        hl = pack_word64(f0 + rowoff + cell0 - 64);       // cells [c0-64, c0)
    if (lane == 31 && !last)
        hr = pack_word64(f0 + rowoff + cell0 + CCELLS);   // cells [c0+1024, c0+1088)

    // ---- 63 CA steps, emitting the fp32 slab each step ----
    for (int t = 1; t < TT; t++) {
        u32 p = __shfl_up_sync(FULLM, cur, 1);
        u32 n = __shfl_down_sync(FULLM, cur, 1);
        if (lane == 0)  p = (u32)(hl >> 32);   // so p>>31 = hl bit 63
        if (lane == 31) n = (u32)hr;           // so n<<31 picks hr bit 0

        const u32 L = (cur << 1) | (p >> 31);
        const u32 R = (cur >> 1) | (n << 31);
        const u32 nx = mux3<u32>(L, cur, R, m0, m1, m2, m3, m4, m5, m6, m7);

        // Evolve halo words (beyond-halo treated as 0; true row edges stay 0).
        if (lane == 0 && !first) {
            const u64 hL = hl << 1;
            const u64 hR = (hl >> 1) | ((u64)(cur & 1u) << 63);
            hl = mux3<u64>(hL, hl, hR, M0, M1, M2, M3, M4, M5, M6, M7);
        }
        if (lane == 31 && !last) {
            const u64 hL = (hr << 1) | (u64)(cur >> 31);
            const u64 hR = hr >> 1;
            hr = mux3<u64>(hL, hr, hR, M0, M1, M2, M3, M4, M5, M6, M7);
        }
        cur = nx;

        // Coalesced output: float4 #idx covers cells 4*idx..4*idx+3 ->
        // source word idx>>3, nibble (idx&7). Broadcast shuffles.
        float4* ot = (float4*)(out + (size_t)t * (BB * NN) + rowoff + cell0);
#pragma unroll
        for (int k = 0; k < 8; k++) {
            const int idx = k * 32 + lane;
            const u32 w = __shfl_sync(FULLM, cur, idx >> 3);
            const u32 nib = (w >> ((idx & 7) * 4)) & 0xFu;
            float4 v;
            v.x = (nib & 1u) ? 1.0f : 0.0f;
            v.y = (nib & 2u) ? 1.0f : 0.0f;
            v.z = (nib & 4u) ? 1.0f : 0.0f;
            v.w = (nib & 8u) ? 1.0f : 0.0f;
            __stcs(ot + idx, v);
        }
    }
}

extern "C" void kernel_launch(void* const* d_in, const int* in_sizes, int n_in,
                              void* d_out, int out_size) {
    const float* f0 = (const float*)d_in[0];
    const float* W1 = (const float*)d_in[1];
    const float* b1 = (const float*)d_in[2];
    const float* W2 = (const float*)d_in[3];
    const float* b2 = (const float*)d_in[4];
    float* out = (float*)d_out;

    // 32 rows x 64 chunks = 2048 warps; 2 warps/CTA -> 1024 CTAs.
    // 1024 = 148*6 + 136 -> 6-7 CTAs per SM, ~1% imbalance, all SMs busy.
    fused_kernel<<<1024, 64>>>(f0, W1, b1, W2, b2, out);
}

// round 5
// speedup vs baseline: 1.0010x; 1.0010x over previous
#include <cuda_runtime.h>

// Shape fixed by setup_inputs: B=32, N=65536, T=64, HIDDEN=16.
#define BB      32
#define NN      65536
#define TT      64
#define CHUNKS  32                 // chunks per row (2048 cells each)
#define CWORDS  32                 // u64 words per chunk
#define FULLM   0xFFFFFFFFu

typedef unsigned long long u64;

// 3-input mux over constant masks: next_bit = msk[L*4 + C*2 + R].
__device__ __forceinline__ u64 mux3(u64 L, u64 C, u64 R,
                                    u64 m0, u64 m1, u64 m2, u64 m3,
                                    u64 m4, u64 m5, u64 m6, u64 m7) {
    u64 x0 = (R & m1) | (~R & m0);
    u64 x1 = (R & m3) | (~R & m2);
    u64 x2 = (R & m5) | (~R & m4);
    u64 x3 = (R & m7) | (~R & m6);
    u64 y0 = (C & x1) | (~C & x0);
    u64 y1 = (C & x3) | (~C & x2);
    return (L & y1) | (~L & y0);
}

__device__ __forceinline__ u64 pack_word(const float* __restrict__ p) {
    u64 w = 0ULL;
    const float4* p4 = (const float4*)p;
#pragma unroll
    for (int k = 0; k < 16; k++) {
        float4 v = p4[k];
        u64 q = 0ULL;
        if (v.x > 0.5f) q |= 1ULL;
        if (v.y > 0.5f) q |= 2ULL;
        if (v.z > 0.5f) q |= 4ULL;
        if (v.w > 0.5f) q |= 8ULL;
        w |= q << (4 * k);
    }
    return w;
}

// One single-warp CTA per (row, chunk-of-2048-cells). Each lane owns one u64
// word (64 cells); neighbors via shuffle. Lanes 0/31 carry one u64 halo word
// each (63 steps < 64 halo bits, so beyond-halo garbage never reaches the
// chunk). Every step writes the chunk's fp32 slab with streaming stores.
__global__ __launch_bounds__(32) void fused_kernel(
    const float* __restrict__ f0,
    const float* __restrict__ W1,   // (3,16)
    const float* __restrict__ b1,   // (16,)
    const float* __restrict__ W2,   // (16,1)
    const float* __restrict__ b2,   // (1,)
    float* __restrict__ out)
{
    const int lane = threadIdx.x;
    const int gw   = blockIdx.x;                    // global warp 0..1023
    const int row  = gw >> 5;                       // batch row
    const int ch   = gw & (CHUNKS - 1);             // chunk within row
    const bool first = (ch == 0), last = (ch == CHUNKS - 1);

    // Every lane computes the full 8-entry truth table in registers
    // (redundant but ~650 FLOPs once; no smem, no barrier).
    u64 msk[8];
#pragma unroll
    for (int p = 0; p < 8; p++) {
        const float l = (float)((p >> 2) & 1);
        const float c = (float)((p >> 1) & 1);
        const float r = (float)(p & 1);
        float logit = b2[0];
#pragma unroll
        for (int h = 0; h < 16; h++) {
            float v = fmaf(l, W1[h], fmaf(c, W1[16 + h], fmaf(r, W1[32 + h], b1[h])));
            logit = fmaf(W2[h], fmaxf(v, 0.0f), logit);
        }
        msk[p] = (logit > 0.0f) ? ~0ULL : 0ULL;
    }
    const u64 m0 = msk[0], m1 = msk[1], m2 = msk[2], m3 = msk[3];
    const u64 m4 = msk[4], m5 = msk[5], m6 = msk[6], m7 = msk[7];

    const size_t rowoff = (size_t)row * NN;
    const int cell0 = ch * (CWORDS * 64);           // first cell of chunk

    // ---- t = 0 slab: copy f0 chunk verbatim (coalesced) ----
    const float4* src4 = (const float4*)(f0 + rowoff + cell0);
    float4* dst4 = (float4*)(out + rowoff + cell0);
#pragma unroll
    for (int k = 0; k < 16; k++)
        __stcs(dst4 + k * 32 + lane, __ldg(src4 + k * 32 + lane));

    // ---- pack this lane's word + halo words on lanes 0/31 ----
    u64 cur = pack_word(f0 + rowoff + cell0 + lane * 64);
    u64 hl = 0ULL, hr = 0ULL;
    if (lane == 0 && !first)
        hl = pack_word(f0 + rowoff + cell0 - 64);
    if (lane == 31 && !last)
        hr = pack_word(f0 + rowoff + cell0 + CWORDS * 64);

    // ---- 63 CA steps, emitting the fp32 slab each step ----
    for (int t = 1; t < TT; t++) {
        u64 p = __shfl_up_sync(FULLM, cur, 1);
        u64 n = __shfl_down_sync(FULLM, cur, 1);
        if (lane == 0)  p = hl;
        if (lane == 31) n = hr;

        const u64 L = (cur << 1) | (p >> 63);
        const u64 R = (cur >> 1) | (n << 63);
        const u64 nx = mux3(L, cur, R, m0, m1, m2, m3, m4, m5, m6, m7);

        // Evolve halo words (beyond-halo treated as 0; true row edges stay 0).
        if (lane == 0 && !first) {
            const u64 hL = hl << 1;
            const u64 hR = (hl >> 1) | (cur << 63);
            hl = mux3(hL, hl, hR, m0, m1, m2, m3, m4, m5, m6, m7);
        }
        if (lane == 31 && !last) {
            const u64 hL = (hr << 1) | (cur >> 63);
            const u64 hR = hr >> 1;
            hr = mux3(hL, hr, hR, m0, m1, m2, m3, m4, m5, m6, m7);
        }
        cur = nx;

        // Coalesced output: float4 #idx covers cells 4*idx..4*idx+3 ->
        // source word idx>>4, nibble (idx&15). Broadcast shuffles.
        float4* ot = (float4*)(out + (size_t)t * (BB * NN) + rowoff + cell0);
#pragma unroll
        for (int k = 0; k < 16; k++) {
            const int idx = k * 32 + lane;
            const u64 w = __shfl_sync(FULLM, cur, idx >> 4);
            const unsigned int nib = (unsigned int)(w >> ((idx & 15) * 4)) & 0xFu;
            float4 v;
            v.x = (nib & 1u) ? 1.0f : 0.0f;
            v.y = (nib & 2u) ? 1.0f : 0.0f;
            v.z = (nib & 4u) ? 1.0f : 0.0f;
            v.w = (nib & 8u) ? 1.0f : 0.0f;
            __stcs(ot + idx, v);
        }
    }
}

extern "C" void kernel_launch(void* const* d_in, const int* in_sizes, int n_in,
                              void* d_out, int out_size) {
    const float* f0 = (const float*)d_in[0];
    const float* W1 = (const float*)d_in[1];
    const float* b1 = (const float*)d_in[2];
    const float* W2 = (const float*)d_in[3];
    const float* b2 = (const float*)d_in[4];
    float* out = (float*)d_out;

    // 32 rows x 32 chunks = 1024 warps, one warp per CTA.
    // 1024 = 148*6 + 136 -> 6-7 CTAs per SM, ~1% tail imbalance, all SMs busy.
    fused_kernel<<<1024, 32>>>(f0, W1, b1, W2, b2, out);
}

// round 8
// speedup vs baseline: 1.0246x; 1.0236x over previous
#include <cuda_runtime.h>

// Shape fixed by setup_inputs: B=32, N=65536, T=64, HIDDEN=16.
#define BB      32
#define NN      65536
#define TT      64
#define CHUNKS  32                 // chunks per row (2048 cells each)
#define CWORDS  32                 // u64 words per chunk
#define NWARPS  1024               // total work units (32 rows x 32 chunks)
#define WPB     7                  // warps per CTA
#define FULLM   0xFFFFFFFFu

typedef unsigned long long u64;

// 3-input mux over constant masks: next_bit = msk[L*4 + C*2 + R].
__device__ __forceinline__ u64 mux3(u64 L, u64 C, u64 R,
                                    u64 m0, u64 m1, u64 m2, u64 m3,
                                    u64 m4, u64 m5, u64 m6, u64 m7) {
    u64 x0 = (R & m1) | (~R & m0);
    u64 x1 = (R & m3) | (~R & m2);
    u64 x2 = (R & m5) | (~R & m4);
    u64 x3 = (R & m7) | (~R & m6);
    u64 y0 = (C & x1) | (~C & x0);
    u64 y1 = (C & x3) | (~C & x2);
    return (L & y1) | (~L & y0);
}

__device__ __forceinline__ u64 pack_word(const float* __restrict__ p) {
    u64 w = 0ULL;
    const float4* p4 = (const float4*)p;
#pragma unroll
    for (int k = 0; k < 16; k++) {
        float4 v = p4[k];
        u64 q = 0ULL;
        if (v.x > 0.5f) q |= 1ULL;
        if (v.y > 0.5f) q |= 2ULL;
        if (v.z > 0.5f) q |= 4ULL;
        if (v.w > 0.5f) q |= 8ULL;
        w |= q << (4 * k);
    }
    return w;
}

// 7 warps per CTA, each warp owns one chunk of 2048 cells (u64 per lane,
// neighbors via shuffle). CTA's 7 chunks are globally consecutive, so each
// SM emits one contiguous ~57KB write stream per time step (DRAM locality).
// Lanes 0/31 carry one u64 halo word each — 63 steps < 64 halo bits, so
// beyond-halo garbage never reaches the chunk.
__global__ __launch_bounds__(WPB * 32) void fused_kernel(
    const float* __restrict__ f0,
    const float* __restrict__ W1,   // (3,16)
    const float* __restrict__ b1,   // (16,)
    const float* __restrict__ W2,   // (16,1)
    const float* __restrict__ b2,   // (1,)
    float* __restrict__ out)
{
    __shared__ u64 smsk[8];
    const int tid = threadIdx.x;

    // Collapse the MLP controller to an 8-entry truth table (once per CTA).
    if (tid < 8) {
        const float l = (float)((tid >> 2) & 1);
        const float c = (float)((tid >> 1) & 1);
        const float r = (float)(tid & 1);
        float logit = b2[0];
#pragma unroll
        for (int h = 0; h < 16; h++) {
            float v = fmaf(l, W1[h], fmaf(c, W1[16 + h], fmaf(r, W1[32 + h], b1[h])));
            logit = fmaf(W2[h], fmaxf(v, 0.0f), logit);
        }
        smsk[tid] = (logit > 0.0f) ? ~0ULL : 0ULL;
    }
    __syncthreads();

    const int gw = blockIdx.x * WPB + (tid >> 5);   // global warp / chunk id
    if (gw >= NWARPS) return;
    const int lane = tid & 31;
    const int row  = gw >> 5;                       // batch row
    const int ch   = gw & (CHUNKS - 1);             // chunk within row
    const bool first = (ch == 0), last = (ch == CHUNKS - 1);

    const u64 m0 = smsk[0], m1 = smsk[1], m2 = smsk[2], m3 = smsk[3];
    const u64 m4 = smsk[4], m5 = smsk[5], m6 = smsk[6], m7 = smsk[7];

    const size_t rowoff = (size_t)row * NN;
    const int cell0 = ch * (CWORDS * 64);           // first cell of chunk

    // ---- t = 0 slab: copy f0 chunk verbatim (coalesced) ----
    const float4* src4 = (const float4*)(f0 + rowoff + cell0);
    float4* dst4 = (float4*)(out + rowoff + cell0);
#pragma unroll
    for (int k = 0; k < 16; k++)
        __stcs(dst4 + k * 32 + lane, __ldg(src4 + k * 32 + lane));

    // ---- pack this lane's word + halo words on lanes 0/31 ----
    u64 cur = pack_word(f0 + rowoff + cell0 + lane * 64);
    u64 hl = 0ULL, hr = 0ULL;
    if (lane == 0 && !first)
        hl = pack_word(f0 + rowoff + cell0 - 64);
    if (lane == 31 && !last)
        hr = pack_word(f0 + rowoff + cell0 + CWORDS * 64);

    // ---- 63 CA steps, emitting the fp32 slab each step ----
    for (int t = 1; t < TT; t++) {
        u64 p = __shfl_up_sync(FULLM, cur, 1);
        u64 n = __shfl_down_sync(FULLM, cur, 1);
        if (lane == 0)  p = hl;
        if (lane == 31) n = hr;

        const u64 L = (cur << 1) | (p >> 63);
        const u64 R = (cur >> 1) | (n << 63);
        const u64 nx = mux3(L, cur, R, m0, m1, m2, m3, m4, m5, m6, m7);

        // Evolve halo words (beyond-halo treated as 0; true row edges stay 0).
        if (lane == 0 && !first) {
            const u64 hL = hl << 1;
            const u64 hR = (hl >> 1) | (cur << 63);
            hl = mux3(hL, hl, hR, m0, m1, m2, m3, m4, m5, m6, m7);
        }
        if (lane == 31 && !last) {
            const u64 hL = (hr << 1) | (cur >> 63);
            const u64 hR = hr >> 1;
            hr = mux3(hL, hr, hR, m0, m1, m2, m3, m4, m5, m6, m7);
        }
        cur = nx;

        // Coalesced output: float4 #idx covers cells 4*idx..4*idx+3 ->
        // source word idx>>4, nibble (idx&15). Broadcast shuffles.
        float4* ot = (float4*)(out + (size_t)t * (BB * NN) + rowoff + cell0);
#pragma unroll
        for (int k = 0; k < 16; k++) {
            const int idx = k * 32 + lane;
            const u64 w = __shfl_sync(FULLM, cur, idx >> 4);
            const unsigned int nib = (unsigned int)(w >> ((idx & 15) * 4)) & 0xFu;
            float4 v;
            v.x = (nib & 1u) ? 1.0f : 0.0f;
            v.y = (nib & 2u) ? 1.0f : 0.0f;
            v.z = (nib & 4u) ? 1.0f : 0.0f;
            v.w = (nib & 8u) ? 1.0f : 0.0f;
            __stcs(ot + idx, v);
        }
    }
}

extern "C" void kernel_launch(void* const* d_in, const int* in_sizes, int n_in,
                              void* d_out, int out_size) {
    const float* f0 = (const float*)d_in[0];
    const float* W1 = (const float*)d_in[1];
    const float* b1 = (const float*)d_in[2];
    const float* W2 = (const float*)d_in[3];
    const float* b2 = (const float*)d_in[4];
    float* out = (float*)d_out;

    // 1024 chunks in 7-warp CTAs: 147 CTAs -> one wave on 148 SMs, each CTA's
    // chunks globally consecutive (contiguous per-SM write stream).
    const int nblocks = (NWARPS + WPB - 1) / WPB;   // 147
    fused_kernel<<<nblocks, WPB * 32>>>(f0, W1, b1, W2, b2, out);
}

// round 9
// speedup vs baseline: 1.0257x; 1.0010x over previous
#include <cuda_runtime.h>

// Shape fixed by setup_inputs: B=32, N=65536, T=64, HIDDEN=16.
#define BB      32
#define NN      65536
#define TT      64
#define ROWWORDS 1024              // u64 words per row
#define CPR     37                 // chunks per row: 36 x 28 words + 1 x 16 words
#define NWBIG   28                 // words in chunks 0..35
#define NWSML   16                 // words in chunk 36
#define NWARPS  (32 * CPR)         // 1184 = 148 CTAs x 8 warps, exact
#define FULLM   0xFFFFFFFFu

typedef unsigned long long u64;

// 3-input mux over constant masks: next_bit = msk[L*4 + C*2 + R].
__device__ __forceinline__ u64 mux3(u64 L, u64 C, u64 R,
                                    u64 m0, u64 m1, u64 m2, u64 m3,
                                    u64 m4, u64 m5, u64 m6, u64 m7) {
    u64 x0 = (R & m1) | (~R & m0);
    u64 x1 = (R & m3) | (~R & m2);
    u64 x2 = (R & m5) | (~R & m4);
    u64 x3 = (R & m7) | (~R & m6);
    u64 y0 = (C & x1) | (~C & x0);
    u64 y1 = (C & x3) | (~C & x2);
    return (L & y1) | (~L & y0);
}

__device__ __forceinline__ u64 pack_word(const float* __restrict__ p) {
    u64 w = 0ULL;
    const float4* p4 = (const float4*)p;
#pragma unroll
    for (int k = 0; k < 16; k++) {
        float4 v = p4[k];
        u64 q = 0ULL;
        if (v.x > 0.5f) q |= 1ULL;
        if (v.y > 0.5f) q |= 2ULL;
        if (v.z > 0.5f) q |= 4ULL;
        if (v.w > 0.5f) q |= 8ULL;
        w |= q << (4 * k);
    }
    return w;
}

// Per-warp body for a chunk of NW u64 words. Lanes [0,NW) own one word each;
// neighbors via shuffle; lanes 0 / NW-1 carry one u64 halo word each (63
// steps < 64 halo bits -> beyond-halo garbage never reaches the chunk).
// Every step writes the chunk's fp32 slab with streaming float4 stores.
template <int NW>
__device__ __forceinline__ void run_chunk(
    const float* __restrict__ f0, float* __restrict__ out,
    int lane, size_t rowoff, int cell0, bool first, bool last,
    u64 m0, u64 m1, u64 m2, u64 m3, u64 m4, u64 m5, u64 m6, u64 m7)
{
    // ---- t = 0 slab: copy f0 chunk verbatim (coalesced) ----
    const float4* src4 = (const float4*)(f0 + rowoff + cell0);
    float4* dst4 = (float4*)(out + rowoff + cell0);
#pragma unroll
    for (int k = 0; k < NW / 2; k++)
        __stcs(dst4 + k * 32 + lane, __ldg(src4 + k * 32 + lane));

    // ---- pack this lane's word + halo words (guard OOB for lanes >= NW) ----
    u64 cur = 0ULL;
    if (lane < NW)
        cur = pack_word(f0 + rowoff + cell0 + lane * 64);
    u64 hl = 0ULL, hr = 0ULL;
    if (lane == 0 && !first)
        hl = pack_word(f0 + rowoff + cell0 - 64);
    if (lane == NW - 1 && !last)
        hr = pack_word(f0 + rowoff + cell0 + NW * 64);

    // ---- 63 CA steps, emitting the fp32 slab each step ----
    for (int t = 1; t < TT; t++) {
        u64 p = __shfl_up_sync(FULLM, cur, 1);
        u64 n = __shfl_down_sync(FULLM, cur, 1);
        if (lane == 0)      p = hl;
        if (lane == NW - 1) n = hr;

        const u64 L = (cur << 1) | (p >> 63);
        const u64 R = (cur >> 1) | (n << 63);
        const u64 nx = mux3(L, cur, R, m0, m1, m2, m3, m4, m5, m6, m7);

        // Evolve halo words (beyond-halo treated as 0; true row edges stay 0).
        if (lane == 0 && !first) {
            const u64 hL = hl << 1;
            const u64 hR = (hl >> 1) | (cur << 63);
            hl = mux3(hL, hl, hR, m0, m1, m2, m3, m4, m5, m6, m7);
        }
        if (lane == NW - 1 && !last) {
            const u64 hL = (hr << 1) | (cur >> 63);
            const u64 hR = hr >> 1;
            hr = mux3(hL, hr, hR, m0, m1, m2, m3, m4, m5, m6, m7);
        }
        cur = nx;

        // Coalesced output: float4 #idx covers cells 4*idx..4*idx+3 ->
        // source word idx>>4, nibble (idx&15). Broadcast shuffles.
        float4* ot = (float4*)(out + (size_t)t * (BB * NN) + rowoff + cell0);
#pragma unroll
        for (int k = 0; k < NW / 2; k++) {
            const int idx = k * 32 + lane;
            const u64 w = __shfl_sync(FULLM, cur, idx >> 4);
            const unsigned int nib = (unsigned int)(w >> ((idx & 15) * 4)) & 0xFu;
            float4 v;
            v.x = (nib & 1u) ? 1.0f : 0.0f;
            v.y = (nib & 2u) ? 1.0f : 0.0f;
            v.z = (nib & 4u) ? 1.0f : 0.0f;
            v.w = (nib & 8u) ? 1.0f : 0.0f;
            __stcs(ot + idx, v);
        }
    }
}

// 8 warps per CTA (2 per SMSP — balanced), one CTA per SM, 148 CTAs exactly.
// Each warp owns one chunk; a CTA's 8 chunks are globally consecutive.
__global__ __launch_bounds__(256) void fused_kernel(
    const float* __restrict__ f0,
    const float* __restrict__ W1,   // (3,16)
    const float* __restrict__ b1,   // (16,)
    const float* __restrict__ W2,   // (16,1)
    const float* __restrict__ b2,   // (1,)
    float* __restrict__ out)
{
    __shared__ u64 smsk[8];
    const int tid = threadIdx.x;

    // Collapse the MLP controller to an 8-entry truth table (once per CTA).
    if (tid < 8) {
        const float l = (float)((tid >> 2) & 1);
        const float c = (float)((tid >> 1) & 1);
        const float r = (float)(tid & 1);
        float logit = b2[0];
#pragma unroll
        for (int h = 0; h < 16; h++) {
            float v = fmaf(l, W1[h], fmaf(c, W1[16 + h], fmaf(r, W1[32 + h], b1[h])));
            logit = fmaf(W2[h], fmaxf(v, 0.0f), logit);
        }
        smsk[tid] = (logit > 0.0f) ? ~0ULL : 0ULL;
    }
    __syncthreads();

    const u64 m0 = smsk[0], m1 = smsk[1], m2 = smsk[2], m3 = smsk[3];
    const u64 m4 = smsk[4], m5 = smsk[5], m6 = smsk[6], m7 = smsk[7];

    const int gw   = blockIdx.x * 8 + (tid >> 5);   // 0..1183, exact
    const int lane = tid & 31;
    const int row  = gw / CPR;                      // batch row
    const int ch   = gw - row * CPR;                // chunk 0..36 within row

    const size_t rowoff = (size_t)row * NN;
    const int cell0 = ch * (NWBIG * 64);            // chunk 36 starts at word 1008

    const bool first = (ch == 0);

    if (ch < CPR - 1) {
        run_chunk<NWBIG>(f0, out, lane, rowoff, cell0, first, false,
                         m0, m1, m2, m3, m4, m5, m6, m7);
    } else {
        run_chunk<NWSML>(f0, out, lane, rowoff, cell0, false, true,
                         m0, m1, m2, m3, m4, m5, m6, m7);
    }
}

extern "C" void kernel_launch(void* const* d_in, const int* in_sizes, int n_in,
                              void* d_out, int out_size) {
    const float* f0 = (const float*)d_in[0];
    const float* W1 = (const float*)d_in[1];
    const float* b1 = (const float*)d_in[2];
    const float* W2 = (const float*)d_in[3];
    const float* b2 = (const float*)d_in[4];
    float* out = (float*)d_out;

    // 1184 warps = 148 CTAs x 8 warps: one 256-thread CTA per SM,
    // 2 warps per SMSP on every SM (the R2 per-SM shape, full coverage).
    fused_kernel<<<148, 256>>>(f0, W1, b1, W2, b2, out);
}